// round 4
// baseline (speedup 1.0000x reference)
#include <cuda_runtime.h>
#include <cuda_bf16.h>

// L1OrderLoss (Chamfer-style L1, PTS_DIM=2): pred/target [8192,128] f32.
// Per row (64 2-D points): dist_1[i,c]=min_j|p[i,c]-t[j,c]|, dist_2[j,c]=min_i|.|
// out = 0.5*(sum d1 + sum d2) / (N*P*2) / 64
//
// R4: fma-pipe was the binding floor (all FADD/FMNMX at rt_SMSP=2).
// Rebalance: x-coordinate min stays on fma pipe (FMNMX |src|), y-coordinate
// min moves to ALU pipe (LOP3 abs-mask + IMNMX.U32 on bit patterns — valid
// because IEEE ordering == u32 ordering for non-negative floats).

#define NROWS   8192
#define PPTS    64
#define RPB     4
#define THREADS (RPB * PPTS)   // 256

#define OUT_SCALE (0.5f / (8192.0f * 128.0f * 64.0f))
#define FLT_MAX_BITS 0x7F7FFFFFu

__global__ void zero_out_kernel(float* out) {
    out[0] = 0.0f;
}

// (rx, ry) = packed f32x2 add of two b64-packed float pairs.
__device__ __forceinline__ void addx2p(unsigned long long a, unsigned long long b,
                                       float& rx, float& ry) {
    asm("{\n\t"
        ".reg .b64 rc;\n\t"
        "add.rn.f32x2 rc, %2, %3;\n\t"
        "mov.b64 {%0, %1}, rc;\n\t"
        "}"
        : "=f"(rx), "=f"(ry)
        : "l"(a), "l"(b));
}

__global__ __launch_bounds__(THREADS, 8)
void l1order_kernel(const float* __restrict__ pred,
                    const float* __restrict__ target,
                    float* __restrict__ out)
{
    __shared__ __align__(16) float2 ps[RPB][PPTS];    // pred points
    __shared__ __align__(16) float2 nts[RPB][PPTS];   // NEGATED target points
    __shared__ float warp_sums[THREADS / 32];

    const int tid = threadIdx.x;
    const int r   = tid >> 6;
    const int k   = tid & 63;
    const int row = blockIdx.x * RPB + r;

    const float2* predv   = reinterpret_cast<const float2*>(pred);
    const float2* targetv = reinterpret_cast<const float2*>(target);
    float2 p = predv[row * PPTS + k];
    float2 t = targetv[row * PPTS + k];
    float ntx = -t.x, nty = -t.y;
    ps[r][k]  = p;
    nts[r][k] = make_float2(ntx, nty);

    unsigned long long pk, ntk;
    asm("mov.b64 %0, {%1, %2};" : "=l"(pk)  : "f"(p.x), "f"(p.y));
    asm("mov.b64 %0, {%1, %2};" : "=l"(ntk) : "f"(ntx), "f"(nty));

    __syncthreads();

    // x mins on fma pipe (float), y mins on alu pipe (u32 bit patterns).
    // Two independent accumulator sets (a/b) for dependence-chain ILP.
    float        d1xa = 1e30f, d1xb = 1e30f, d2xa = 1e30f, d2xb = 1e30f;
    unsigned int d1ya = FLT_MAX_BITS, d1yb = FLT_MAX_BITS;
    unsigned int d2ya = FLT_MAX_BITS, d2yb = FLT_MAX_BITS;

    const ulonglong2* psv = reinterpret_cast<const ulonglong2*>(&ps[r][0]);
    const ulonglong2* ntv = reinterpret_cast<const ulonglong2*>(&nts[r][0]);

    // One pair-side pair (d1 side + d2 side) for point j, into accumulator set S.
#define PAIR(ntj, pj, d1xS, d1yS, d2xS, d2yS)                              \
    do {                                                                   \
        float ax, ay, bx, by;                                              \
        addx2p(pk, (ntj), ax, ay);      /* p_k - t_j */                    \
        addx2p((pj), ntk, bx, by);      /* p_j - t_k */                    \
        d1xS = fminf(d1xS, fabsf(ax));                       /* fma */     \
        d2xS = fminf(d2xS, fabsf(bx));                       /* fma */     \
        d1yS = min(d1yS, __float_as_uint(ay) & 0x7FFFFFFFu); /* alu */     \
        d2yS = min(d2yS, __float_as_uint(by) & 0x7FFFFFFFu); /* alu */     \
    } while (0)

    #pragma unroll 8
    for (int c = 0; c < PPTS / 2; ++c) {   // 2 points per iteration
        ulonglong2 tt = ntv[c];
        ulonglong2 pp = psv[c];
        PAIR(tt.x, pp.x, d1xa, d1ya, d2xa, d2ya);
        PAIR(tt.y, pp.y, d1xb, d1yb, d2xb, d2yb);
    }
#undef PAIR

    float d1x = fminf(d1xa, d1xb);
    float d2x = fminf(d2xa, d2xb);
    float d1y = __uint_as_float(min(d1ya, d1yb));
    float d2y = __uint_as_float(min(d2ya, d2yb));

    float s = (d1x + d1y) + (d2x + d2y);

    #pragma unroll
    for (int off = 16; off > 0; off >>= 1)
        s += __shfl_down_sync(0xFFFFFFFFu, s, off);

    const int wid = tid >> 5;
    if ((tid & 31) == 0) warp_sums[wid] = s;
    __syncthreads();

    if (wid == 0) {
        float v = (tid < (THREADS / 32)) ? warp_sums[tid] : 0.0f;
        #pragma unroll
        for (int off = 4; off > 0; off >>= 1)
            v += __shfl_down_sync(0xFFFFFFFFu, v, off);
        if (tid == 0)
            atomicAdd(out, v * OUT_SCALE);
    }
}

extern "C" void kernel_launch(void* const* d_in, const int* in_sizes, int n_in,
                              void* d_out, int out_size)
{
    const float* pred   = (const float*)d_in[0];
    const float* target = (const float*)d_in[1];
    float* out = (float*)d_out;

    zero_out_kernel<<<1, 1>>>(out);
    l1order_kernel<<<NROWS / RPB, THREADS>>>(pred, target, out);
}

// round 5
// speedup vs baseline: 1.1359x; 1.1359x over previous
#include <cuda_runtime.h>
#include <cuda_bf16.h>

// L1OrderLoss (Chamfer-style L1, PTS_DIM=2): pred/target [8192,128] f32.
// Per row (64 2-D points): dist_1[i,c]=min_j|p[i,c]-t[j,c]|, dist_2[j,c]=min_i|.|
// out = 0.5*(sum d1 + sum d2) / (N*P*2) / 64
//
// R5: 1 warp per row, 2 points per thread.
//  - halves LDS instruction count (each broadcast feeds 2 chains)
//  - 8 independent FMNMX accumulator chains (ILP)
//  - no mid-kernel __syncthreads (row = 1 warp)
//  - diffs via add.rn.f32x2 on pre-negated targets; mins via scalar FMNMX(|src|)

#define NROWS   8192
#define PPTS    64
#define RPB     4                      // rows (warps) per block
#define THREADS (RPB * 32)             // 128

#define OUT_SCALE (0.5f / (8192.0f * 128.0f * 64.0f))

__global__ void zero_out_kernel(float* out) {
    out[0] = 0.0f;
}

// (rx, ry) = packed f32x2 add of two b64-packed float pairs.
__device__ __forceinline__ void addx2p(unsigned long long a, unsigned long long b,
                                       float& rx, float& ry) {
    asm("{\n\t"
        ".reg .b64 rc;\n\t"
        "add.rn.f32x2 rc, %2, %3;\n\t"
        "mov.b64 {%0, %1}, rc;\n\t"
        "}"
        : "=f"(rx), "=f"(ry)
        : "l"(a), "l"(b));
}

__global__ __launch_bounds__(THREADS, 8)
void l1order_kernel(const float* __restrict__ pred,
                    const float* __restrict__ target,
                    float* __restrict__ out)
{
    __shared__ __align__(16) float2 ps[RPB][PPTS];    // pred points
    __shared__ __align__(16) float2 nts[RPB][PPTS];   // NEGATED target points
    __shared__ float warp_sums[RPB];

    const int tid = threadIdx.x;
    const int w   = tid >> 5;        // warp = local row
    const int l   = tid & 31;        // lane; owns points 2l and 2l+1
    const int row = blockIdx.x * RPB + w;

    // One float4 per array per thread = points 2l, 2l+1 (coalesced 512B/warp).
    const float4* predv4   = reinterpret_cast<const float4*>(pred);
    const float4* targetv4 = reinterpret_cast<const float4*>(target);
    float4 P = predv4[row * 32 + l];
    float4 T = targetv4[row * 32 + l];
    float4 NT = make_float4(-T.x, -T.y, -T.z, -T.w);

    reinterpret_cast<float4*>(&ps[w][0])[l]  = P;    // STS.128
    reinterpret_cast<float4*>(&nts[w][0])[l] = NT;   // STS.128

    // Pack own 2 pred points and own 2 negated targets into b64.
    unsigned long long pk0, pk1, ntk0, ntk1;
    asm("mov.b64 %0, {%1, %2};" : "=l"(pk0)  : "f"(P.x),  "f"(P.y));
    asm("mov.b64 %0, {%1, %2};" : "=l"(pk1)  : "f"(P.z),  "f"(P.w));
    asm("mov.b64 %0, {%1, %2};" : "=l"(ntk0) : "f"(NT.x), "f"(NT.y));
    asm("mov.b64 %0, {%1, %2};" : "=l"(ntk1) : "f"(NT.z), "f"(NT.w));

    __syncwarp();

    // 8 independent min chains.
    float d1x0 = 1e30f, d1y0 = 1e30f, d1x1 = 1e30f, d1y1 = 1e30f;
    float d2x0 = 1e30f, d2y0 = 1e30f, d2x1 = 1e30f, d2y1 = 1e30f;

    const ulonglong2* psv = reinterpret_cast<const ulonglong2*>(&ps[w][0]);
    const ulonglong2* ntv = reinterpret_cast<const ulonglong2*>(&nts[w][0]);

    #pragma unroll 4
    for (int c = 0; c < PPTS / 2; ++c) {
        ulonglong2 tt = ntv[c];   // neg targets 2c, 2c+1 (one LDS.128, broadcast)
        ulonglong2 pp = psv[c];   // preds       2c, 2c+1 (one LDS.128, broadcast)

        float ax, ay;
        // d1 side: own preds vs targets 2c, 2c+1
        addx2p(pk0, tt.x, ax, ay);
        d1x0 = fminf(d1x0, fabsf(ax));  d1y0 = fminf(d1y0, fabsf(ay));
        addx2p(pk0, tt.y, ax, ay);
        d1x0 = fminf(d1x0, fabsf(ax));  d1y0 = fminf(d1y0, fabsf(ay));
        addx2p(pk1, tt.x, ax, ay);
        d1x1 = fminf(d1x1, fabsf(ax));  d1y1 = fminf(d1y1, fabsf(ay));
        addx2p(pk1, tt.y, ax, ay);
        d1x1 = fminf(d1x1, fabsf(ax));  d1y1 = fminf(d1y1, fabsf(ay));

        // d2 side: preds 2c, 2c+1 vs own targets
        addx2p(pp.x, ntk0, ax, ay);
        d2x0 = fminf(d2x0, fabsf(ax));  d2y0 = fminf(d2y0, fabsf(ay));
        addx2p(pp.y, ntk0, ax, ay);
        d2x0 = fminf(d2x0, fabsf(ax));  d2y0 = fminf(d2y0, fabsf(ay));
        addx2p(pp.x, ntk1, ax, ay);
        d2x1 = fminf(d2x1, fabsf(ax));  d2y1 = fminf(d2y1, fabsf(ay));
        addx2p(pp.y, ntk1, ax, ay);
        d2x1 = fminf(d2x1, fabsf(ax));  d2y1 = fminf(d2y1, fabsf(ay));
    }

    float s = ((d1x0 + d1y0) + (d1x1 + d1y1))
            + ((d2x0 + d2y0) + (d2x1 + d2y1));

    #pragma unroll
    for (int off = 16; off > 0; off >>= 1)
        s += __shfl_down_sync(0xFFFFFFFFu, s, off);

    if (l == 0) warp_sums[w] = s;
    __syncthreads();

    if (tid == 0) {
        float v = (warp_sums[0] + warp_sums[1]) + (warp_sums[2] + warp_sums[3]);
        atomicAdd(out, v * OUT_SCALE);
    }
}

extern "C" void kernel_launch(void* const* d_in, const int* in_sizes, int n_in,
                              void* d_out, int out_size)
{
    const float* pred   = (const float*)d_in[0];
    const float* target = (const float*)d_in[1];
    float* out = (float*)d_out;

    zero_out_kernel<<<1, 1>>>(out);
    l1order_kernel<<<NROWS / RPB, THREADS>>>(pred, target, out);
}